// round 1
// baseline (speedup 1.0000x reference)
#include <cuda_runtime.h>

// PWLU channelwise piecewise-linear unit.
// x: [B=32, C=256, H=56, W=56] f32 (contiguous), points: [C=256, P=7] f32.
// out[b,c,h,w] = left[c][r] + (xn - r) * diff[c][r]
//   xn = (x + BOUND) / region_length,  r = (int)clip(xn, 0, R-1)
// BOUND = 2.7, R = 6, region_length = 2*BOUND/R = 0.9.

#define PWLU_BOUND 2.7f
#define PWLU_NREG 6
#define PWLU_NPTS 7
#define PWLU_HW 3136          // 56*56, divisible by 4
#define PWLU_HW4 784          // float4 count per slab
#define PWLU_C 256

__global__ __launch_bounds__(256) void pwlu_kernel(
    const float* __restrict__ x,
    const float* __restrict__ points,
    float* __restrict__ out)
{
    const int slab = blockIdx.x;          // b * C + c
    const int c = slab & (PWLU_C - 1);

    __shared__ float s_left[PWLU_NREG];
    __shared__ float s_diff[PWLU_NREG];
    if (threadIdx.x < PWLU_NREG) {
        const float p0 = points[c * PWLU_NPTS + threadIdx.x];
        const float p1 = points[c * PWLU_NPTS + threadIdx.x + 1];
        s_left[threadIdx.x] = p0;
        s_diff[threadIdx.x] = p1 - p0;
    }
    __syncthreads();

    const float4* __restrict__ xv =
        reinterpret_cast<const float4*>(x + (size_t)slab * PWLU_HW);
    float4* __restrict__ ov =
        reinterpret_cast<float4*>(out + (size_t)slab * PWLU_HW);

    const float inv_rl = (float)PWLU_NREG / (2.0f * PWLU_BOUND);  // 1/0.9
    const float rmax = (float)(PWLU_NREG - 1);

    #pragma unroll 1
    for (int i = threadIdx.x; i < PWLU_HW4; i += 256) {
        float4 v = xv[i];
        float4 o;

        {
            float xn = (v.x + PWLU_BOUND) * inv_rl;
            int r = (int)fminf(fmaxf(xn, 0.0f), rmax);
            float d = xn - (float)r;
            o.x = fmaf(d, s_diff[r], s_left[r]);
        }
        {
            float xn = (v.y + PWLU_BOUND) * inv_rl;
            int r = (int)fminf(fmaxf(xn, 0.0f), rmax);
            float d = xn - (float)r;
            o.y = fmaf(d, s_diff[r], s_left[r]);
        }
        {
            float xn = (v.z + PWLU_BOUND) * inv_rl;
            int r = (int)fminf(fmaxf(xn, 0.0f), rmax);
            float d = xn - (float)r;
            o.z = fmaf(d, s_diff[r], s_left[r]);
        }
        {
            float xn = (v.w + PWLU_BOUND) * inv_rl;
            int r = (int)fminf(fmaxf(xn, 0.0f), rmax);
            float d = xn - (float)r;
            o.w = fmaf(d, s_diff[r], s_left[r]);
        }

        ov[i] = o;
    }
}

extern "C" void kernel_launch(void* const* d_in, const int* in_sizes, int n_in,
                              void* d_out, int out_size)
{
    const float* x      = (const float*)d_in[0];
    const float* points = (const float*)d_in[1];
    float* out          = (float*)d_out;

    const int n_slabs = in_sizes[0] / PWLU_HW;   // B * C = 8192
    pwlu_kernel<<<n_slabs, 256>>>(x, points, out);
}

// round 2
// speedup vs baseline: 1.0571x; 1.0571x over previous
#include <cuda_runtime.h>

// PWLU channelwise piecewise-linear unit.
// x: [B=32, C=256, H=56, W=56] f32 (contiguous), points: [C=256, P=7] f32.
// out = left[c][r] + (xn - r) * diff[c][r],
//   xn = (x + 2.7) / 0.9, r = (int)clip(xn, 0, 5)
//
// One block per (b,c) slab of 3136 floats = 784 float4.
// 256 threads: each loads 3 float4 up-front (threads 0..15 a 4th, predicated)
// so the warp has 3-4 independent LDG.128 in flight before any compute.

#define PWLU_NREG 6
#define PWLU_NPTS 7
#define PWLU_HW   3136
#define PWLU_HW4  784
#define PWLU_C    256

__device__ __forceinline__ float pwlu1(float v, const float2* __restrict__ tab)
{
    const float inv_rl = 1.0f / 0.9f;
    const float bias   = 2.7f * (1.0f / 0.9f);   // = 3.0 (region offset)
    float xn = fmaf(v, inv_rl, bias);
    float xc = fminf(fmaxf(xn, 0.0f), 5.0f);
    int   r  = (int)xc;                 // trunc == floor (xc >= 0)
    float d  = xn - (float)r;
    float2 ld = tab[r];                 // (left, diff) in one LDS.64
    return fmaf(d, ld.y, ld.x);
}

__device__ __forceinline__ float4 pwlu4(float4 v, const float2* __restrict__ tab)
{
    float4 o;
    o.x = pwlu1(v.x, tab);
    o.y = pwlu1(v.y, tab);
    o.z = pwlu1(v.z, tab);
    o.w = pwlu1(v.w, tab);
    return o;
}

__global__ __launch_bounds__(256) void pwlu_kernel(
    const float* __restrict__ x,
    const float* __restrict__ points,
    float* __restrict__ out)
{
    const int slab = blockIdx.x;                 // b * C + c
    const int c    = slab & (PWLU_C - 1);
    const int t    = threadIdx.x;

    const float4* __restrict__ xv =
        reinterpret_cast<const float4*>(x) + (size_t)slab * PWLU_HW4;
    float4* __restrict__ ov =
        reinterpret_cast<float4*>(out) + (size_t)slab * PWLU_HW4;

    // ---- front-batched independent global loads (MLP 3-4 per thread) ----
    float4 v0 = xv[t];
    float4 v1 = xv[t + 256];
    float4 v2 = xv[t + 512];
    const bool rem = (t < (PWLU_HW4 - 768));     // 16 leftover float4
    float4 v3;
    if (rem) v3 = xv[t + 768];

    // ---- table setup overlaps with load latency ----
    __shared__ float2 s_tab[PWLU_NREG];
    if (t < PWLU_NREG) {
        float p0 = points[c * PWLU_NPTS + t];
        float p1 = points[c * PWLU_NPTS + t + 1];
        s_tab[t] = make_float2(p0, p1 - p0);
    }
    __syncthreads();

    // ---- compute + store ----
    float4 o0 = pwlu4(v0, s_tab);
    float4 o1 = pwlu4(v1, s_tab);
    float4 o2 = pwlu4(v2, s_tab);
    ov[t]       = o0;
    ov[t + 256] = o1;
    ov[t + 512] = o2;
    if (rem) {
        ov[t + 768] = pwlu4(v3, s_tab);
    }
}

extern "C" void kernel_launch(void* const* d_in, const int* in_sizes, int n_in,
                              void* d_out, int out_size)
{
    const float* x      = (const float*)d_in[0];
    const float* points = (const float*)d_in[1];
    float* out          = (float*)d_out;

    const int n_slabs = in_sizes[0] / PWLU_HW;   // B * C = 8192
    pwlu_kernel<<<n_slabs, 256>>>(x, points, out);
}